// round 12
// baseline (speedup 1.0000x reference)
#include <cuda_runtime.h>
#include <cuda_bf16.h>
#include <math.h>
#include <stdint.h>

// Fixed problem shapes
#define CC   768
#define BB   2
#define HH   12
#define DDIM 64
#define NM   4096
#define NX   16384
#define RQ   (NX*BB)   // 32768 rows of x
#define RM   (NM*BB)   // 8192 rows of memory

// ---------------- scratch (device globals; no allocation) ----------------
__device__ float g_q  [RQ*CC];
__device__ float g_k  [RM*CC];
__device__ float g_v  [RM*CC];
__device__ float g_sp [CC];
__device__ float g_kmp[BB*64*CC];
__device__ float g_km [BB*CC];
__device__ float g_kvp[BB*HH*16*DDIM*DDIM];
__device__ float g_kv [BB*HH*DDIM*DDIM];
__device__ float g_vT [BB*CC*NM];
__device__ float g_dT [BB*CC*NM];
__device__ float g_dwc[BB*NM*CC];
__device__ float g_op [RQ*CC];    // out_pre, K-PERMUTED + tf32-rounded

// pre-rounded + K-permuted tf32 operands
__device__ float g_mr [RM*CC];
__device__ float g_wvr[CC*CC];
__device__ float g_wpr[CC*CC];

// bf16 hi/lo split planes (16B-aligned for cp.async)
__device__ __align__(128) __nv_bfloat16 g_xh[RQ*CC],  g_xl[RQ*CC];
__device__ __align__(128) __nv_bfloat16 g_mh[RM*CC],  g_ml[RM*CC];
__device__ __align__(128) __nv_bfloat16 g_wqh[CC*CC], g_wql[CC*CC];
__device__ __align__(128) __nv_bfloat16 g_wkh[CC*CC], g_wkl[CC*CC];

__device__ __forceinline__ uint32_t cvt_tf32(float x) {
    uint32_t r;
    asm("cvt.rna.tf32.f32 %0, %1;" : "=r"(r) : "f"(x));
    return r;
}

// ---------------- softplus of scale ----------------
__global__ void sp_kernel(const float* __restrict__ scale) {
    int i = threadIdx.x;
    float s = scale[i];
    g_sp[i] = (s > 20.f) ? s : log1pf(expf(s));
}

// ---------------- fp32 -> bf16 hi/lo split ----------------
__global__ void split_kernel(const float* __restrict__ src,
                             __nv_bfloat16* __restrict__ hi,
                             __nv_bfloat16* __restrict__ lo, int n4) {
    int i = blockIdx.x * 256 + threadIdx.x;
    if (i >= n4) return;
    float4 v = ((const float4*)src)[i];
    __nv_bfloat16 h0 = __float2bfloat16(v.x);
    __nv_bfloat16 h1 = __float2bfloat16(v.y);
    __nv_bfloat16 h2 = __float2bfloat16(v.z);
    __nv_bfloat16 h3 = __float2bfloat16(v.w);
    __nv_bfloat16 l0 = __float2bfloat16(v.x - __bfloat162float(h0));
    __nv_bfloat16 l1 = __float2bfloat16(v.y - __bfloat162float(h1));
    __nv_bfloat16 l2 = __float2bfloat16(v.z - __bfloat162float(h2));
    __nv_bfloat16 l3 = __float2bfloat16(v.w - __bfloat162float(h3));
    __nv_bfloat162 H0; H0.x = h0; H0.y = h1;
    __nv_bfloat162 H1; H1.x = h2; H1.y = h3;
    __nv_bfloat162 L0; L0.x = l0; L0.y = l1;
    __nv_bfloat162 L1; L1.x = l2; L1.y = l3;
    ((__nv_bfloat162*)hi)[2*i]   = H0;
    ((__nv_bfloat162*)hi)[2*i+1] = H1;
    ((__nv_bfloat162*)lo)[2*i]   = L0;
    ((__nv_bfloat162*)lo)[2*i+1] = L1;
}

// ---------------- fp32 -> RNA tf32-rounded fp32, K-permuted ----------------
// dst slot s within each 32-block holds src k = (s%8)*4 + s/8
// (i.e. s(k) = (k%4)*8 + k/4). Rows are multiples of 32 (CC=768) so blocks
// never straddle rows.
__global__ void round_perm_kernel(const float* __restrict__ src,
                                  float* __restrict__ dst, int n4) {
    int i = blockIdx.x * 256 + threadIdx.x;   // output float4 index
    if (i >= n4) return;
    int f0   = i * 4;
    int s0   = f0 & 31;          // first slot within 32-block (mult of 4)
    int base = f0 & ~31;         // 32-block base (global float idx)
    int k0   = ((s0 & 7) << 2) + (s0 >> 3);
    float4 o;
    o.x = __uint_as_float(cvt_tf32(src[base + k0]));
    o.y = __uint_as_float(cvt_tf32(src[base + k0 + 4]));
    o.z = __uint_as_float(cvt_tf32(src[base + k0 + 8]));
    o.w = __uint_as_float(cvt_tf32(src[base + k0 + 12]));
    ((float4*)dst)[i] = o;
}

// =====================================================================
// bf16 3-term GEMM (m16n8k16): C = Ah*Bh + Ah*Bl + Al*Bh, fp32 accum.
// Single-sync double-buffered pipeline; ldmatrix.x4 loads; term-major MMAs.
// =====================================================================
#define BROW  80
#define BPL   (128*BROW)
#define BSTG  (4*BPL)
#define BSMEM (2*BSTG)

__device__ __forceinline__ void ldm_x4(uint32_t* r, uint32_t addr) {
    asm volatile("ldmatrix.sync.aligned.m8n8.x4.shared.b16 {%0,%1,%2,%3}, [%4];"
                 : "=r"(r[0]), "=r"(r[1]), "=r"(r[2]), "=r"(r[3]) : "r"(addr));
}

__global__ void __launch_bounds__(256) tgemm_bf16_3t(
    const __nv_bfloat16* __restrict__ Ah, const __nv_bfloat16* __restrict__ Al,
    const __nv_bfloat16* __restrict__ Bh, const __nv_bfloat16* __restrict__ Bl,
    float* __restrict__ Cm)
{
    extern __shared__ __align__(128) char bsm[];
    const uint32_t sbase = (uint32_t)__cvta_generic_to_shared(bsm);
    const int tid  = threadIdx.x;
    const int lane = tid & 31;
    const int warp = tid >> 5;
    const int wm = (warp & 1) * 64;
    const int wn = (warp >> 1) * 32;
    const int lr = lane >> 2;
    const int lc = lane & 3;
    const int bm = blockIdx.x * 128;
    const int bn = blockIdx.y * 128;

    const int a_row = lane & 15;
    const int a_ko  = (lane >> 4) * 16;
    const int b_row = (lane & 7) + ((lane >> 4) & 1) * 8;
    const int b_ko  = ((lane >> 3) & 1) * 16;

    float acc[4][4][4];
#pragma unroll
    for (int mt = 0; mt < 4; mt++)
#pragma unroll
        for (int nt = 0; nt < 4; nt++)
#pragma unroll
            for (int e = 0; e < 4; e++) acc[mt][nt][e] = 0.f;

    const int NITER = CC / 32;   // 24

#define BISSUE(IT, BUFI)                                                          \
    do {                                                                           \
        int _k0 = (IT) * 32;                                                       \
        char* _st = bsm + (BUFI) * BSTG;                                           \
        _Pragma("unroll")                                                          \
        for (int _j = 0; _j < 8; _j++) {                                           \
            int _u = tid + 256 * _j;                                               \
            int _seg = _u & 3, _row = (_u >> 2) & 127, _pl = _u >> 9;              \
            const __nv_bfloat16* _src = (_pl == 0) ? Ah : (_pl == 1) ? Al          \
                                        : (_pl == 2) ? Bh : Bl;                    \
            int _r0 = (_pl < 2) ? bm : bn;                                         \
            uint32_t _d = (uint32_t)__cvta_generic_to_shared(                      \
                _st + _pl * BPL + _row * BROW + _seg * 16);                        \
            asm volatile("cp.async.cg.shared.global [%0], [%1], 16;" ::            \
                         "r"(_d),                                                  \
                         "l"(_src + (size_t)(_r0 + _row) * CC + _k0 + _seg * 8));  \
        }                                                                          \
        asm volatile("cp.async.commit_group;");                                    \
    } while (0)

    int buf = 0;
    BISSUE(0, 0);

    for (int it = 0; it < NITER; ++it) {
        asm volatile("cp.async.wait_group 0;");
        __syncthreads();   // data visible AND all warps done reading buf^1
        if (it + 1 < NITER) BISSUE(it + 1, buf ^ 1);

        const uint32_t sAh = sbase + buf * BSTG;
        const uint32_t sAl = sAh + BPL;
        const uint32_t sBh = sAh + 2 * BPL;
        const uint32_t sBl = sAh + 3 * BPL;

#pragma unroll
        for (int ks = 0; ks < 2; ks++) {
            const int kbase = ks * 32;
            uint32_t ah[4][4], al[4][4];
            uint32_t bh[4][2], bl[4][2];
#pragma unroll
            for (int mt = 0; mt < 4; mt++) {
                uint32_t off = (uint32_t)((wm + mt * 16 + a_row) * BROW + kbase + a_ko);
                ldm_x4(ah[mt], sAh + off);
                ldm_x4(al[mt], sAl + off);
            }
#pragma unroll
            for (int ntp = 0; ntp < 2; ntp++) {
                uint32_t off = (uint32_t)((wn + ntp * 16 + b_row) * BROW + kbase + b_ko);
                uint32_t th[4], tl[4];
                ldm_x4(th, sBh + off);
                ldm_x4(tl, sBl + off);
                bh[ntp*2][0]   = th[0]; bh[ntp*2][1]   = th[1];
                bh[ntp*2+1][0] = th[2]; bh[ntp*2+1][1] = th[3];
                bl[ntp*2][0]   = tl[0]; bl[ntp*2][1]   = tl[1];
                bl[ntp*2+1][0] = tl[2]; bl[ntp*2+1][1] = tl[3];
            }
#define BMMA(AF, BF, mt, nt)                                                  \
    asm volatile(                                                             \
        "mma.sync.aligned.m16n8k16.row.col.f32.bf16.bf16.f32 "                \
        "{%0,%1,%2,%3}, {%4,%5,%6,%7}, {%8,%9}, {%0,%1,%2,%3};"               \
        : "+f"(acc[mt][nt][0]), "+f"(acc[mt][nt][1]),                         \
          "+f"(acc[mt][nt][2]), "+f"(acc[mt][nt][3])                          \
        : "r"(AF[mt][0]), "r"(AF[mt][1]), "r"(AF[mt][2]), "r"(AF[mt][3]),     \
          "r"(BF[nt][0]), "r"(BF[nt][1]))
#pragma unroll
            for (int mt = 0; mt < 4; mt++)
#pragma unroll
                for (int nt = 0; nt < 4; nt++) BMMA(ah, bh, mt, nt);
#pragma unroll
            for (int mt = 0; mt < 4; mt++)
#pragma unroll
                for (int nt = 0; nt < 4; nt++) BMMA(ah, bl, mt, nt);
#pragma unroll
            for (int mt = 0; mt < 4; mt++)
#pragma unroll
                for (int nt = 0; nt < 4; nt++) BMMA(al, bh, mt, nt);
#undef BMMA
        }
        buf ^= 1;
    }

#pragma unroll
    for (int mt = 0; mt < 4; mt++) {
#pragma unroll
        for (int nt = 0; nt < 4; nt++) {
            int r0 = bm + wm + mt * 16 + lr;
            int c0 = bn + wn + nt * 8 + 2 * lc;
            float2 v0, v1;
            v0.x = acc[mt][nt][0]; v0.y = acc[mt][nt][1];
            v1.x = acc[mt][nt][2]; v1.y = acc[mt][nt][3];
            *(float2*)&Cm[(size_t)r0 * CC + c0]       = v0;
            *(float2*)&Cm[(size_t)(r0 + 8) * CC + c0] = v1;
        }
    }
#undef BISSUE
}

// =====================================================================
// TF32 GEMM for v/proj. Operands pre-rounded AND K-permuted in gmem:
// slot s holds k=(s%8)*4+s/8, so a float4 at [row*36 + lc*8 + 4g] yields
// a thread's mma frag k-values for ks=2g (x,y) and ks=2g+1 (z,w).
// Single-sync pipeline. 24 LDS.128 + 64 MMA per K32-iter.
// =====================================================================
#define GSTRIDE 36
#define GBUF    (128*GSTRIDE)
#define GSMEM_BYTES (4 * GBUF * 2 * 2)

template <bool ADD_BIAS>
__global__ void __launch_bounds__(256, 2) tgemm_tf32(
    const float* __restrict__ A, const float* __restrict__ W,
    const float* __restrict__ bias, float* __restrict__ Cm, int M)
{
    extern __shared__ float smem[];
    float* As = smem;
    float* Bs = smem + 2 * GBUF;

    const int tid  = threadIdx.x;
    const int lane = tid & 31;
    const int warp = tid >> 5;
    const int wm = (warp & 1) * 64;
    const int wn = (warp >> 1) * 32;
    const int lr = lane >> 2;
    const int lc = lane & 3;
    const int bm = blockIdx.x * 128;
    const int bn = blockIdx.y * 128;

    float acc[4][4][4];
#pragma unroll
    for (int mt = 0; mt < 4; mt++)
#pragma unroll
        for (int nt = 0; nt < 4; nt++)
#pragma unroll
            for (int e = 0; e < 4; e++) acc[mt][nt][e] = 0.f;

    const int NITER = CC / 32;

#define ISSUE_TILE(IT, BUFI)                                                     \
    do {                                                                          \
        int _k0 = (IT) * 32;                                                      \
        float* _dA = As + (BUFI) * GBUF;                                          \
        float* _dB = Bs + (BUFI) * GBUF;                                          \
        _Pragma("unroll")                                                         \
        for (int _l = 0; _l < 4; _l++) {                                          \
            int _lin = tid + _l * 256;                                            \
            int _m = _lin >> 3, _kq = (_lin & 7) << 2;                            \
            uint32_t _da = (uint32_t)__cvta_generic_to_shared(                    \
                _dA + _m * GSTRIDE + _kq);                                        \
            asm volatile("cp.async.cg.shared.global [%0], [%1], 16;" ::           \
                         "r"(_da),                                                \
                         "l"(A + (size_t)(bm + _m) * CC + _k0 + _kq));            \
            uint32_t _db = (uint32_t)__cvta_generic_to_shared(                    \
                _dB + _m * GSTRIDE + _kq);                                        \
            asm volatile("cp.async.cg.shared.global [%0], [%1], 16;" ::           \
                         "r"(_db),                                                \
                         "l"(W + (size_t)(bn + _m) * CC + _k0 + _kq));            \
        }                                                                         \
        asm volatile("cp.async.commit_group;");                                   \
    } while (0)

    int buf = 0;
    ISSUE_TILE(0, 0);

    for (int it = 0; it < NITER; ++it) {
        asm volatile("cp.async.wait_group 0;");
        __syncthreads();
        if (it + 1 < NITER) ISSUE_TILE(it + 1, buf ^ 1);

        const float* cA = As + buf * GBUF;
        const float* cB = Bs + buf * GBUF;

#pragma unroll
        for (int g = 0; g < 2; g++) {
            float4 a4[4][2], b4[4];
#pragma unroll
            for (int mt = 0; mt < 4; mt++) {
                const float* pr = cA + (wm + mt * 16 + lr) * GSTRIDE + lc * 8 + g * 4;
                a4[mt][0] = *(const float4*)pr;
                a4[mt][1] = *(const float4*)(pr + 8 * GSTRIDE);
            }
#pragma unroll
            for (int nt = 0; nt < 4; nt++)
                b4[nt] = *(const float4*)(cB + (wn + nt * 8 + lr) * GSTRIDE + lc * 8 + g * 4);

#pragma unroll
            for (int h = 0; h < 2; h++) {
#pragma unroll
                for (int mt = 0; mt < 4; mt++) {
                    uint32_t a0 = __float_as_uint(h ? a4[mt][0].z : a4[mt][0].x);
                    uint32_t a2 = __float_as_uint(h ? a4[mt][0].w : a4[mt][0].y);
                    uint32_t a1 = __float_as_uint(h ? a4[mt][1].z : a4[mt][1].x);
                    uint32_t a3 = __float_as_uint(h ? a4[mt][1].w : a4[mt][1].y);
#pragma unroll
                    for (int nt = 0; nt < 4; nt++) {
                        uint32_t b0 = __float_as_uint(h ? b4[nt].z : b4[nt].x);
                        uint32_t b1 = __float_as_uint(h ? b4[nt].w : b4[nt].y);
                        asm volatile(
                            "mma.sync.aligned.m16n8k8.row.col.f32.tf32.tf32.f32 "
                            "{%0,%1,%2,%3}, {%4,%5,%6,%7}, {%8,%9}, {%0,%1,%2,%3};"
                            : "+f"(acc[mt][nt][0]), "+f"(acc[mt][nt][1]),
                              "+f"(acc[mt][nt][2]), "+f"(acc[mt][nt][3])
                            : "r"(a0), "r"(a1), "r"(a2), "r"(a3),
                              "r"(b0), "r"(b1));
                    }
                }
            }
        }
        buf ^= 1;
    }

#pragma unroll
    for (int mt = 0; mt < 4; mt++) {
#pragma unroll
        for (int nt = 0; nt < 4; nt++) {
            int r0 = bm + wm + mt * 16 + lr;
            int c0 = bn + wn + nt * 8 + 2 * lc;
            float badd0 = 0.f, badd1 = 0.f;
            if (ADD_BIAS) { badd0 = bias[c0]; badd1 = bias[c0 + 1]; }
            float2 v0, v1;
            v0.x = acc[mt][nt][0] + badd0; v0.y = acc[mt][nt][1] + badd1;
            v1.x = acc[mt][nt][2] + badd0; v1.y = acc[mt][nt][3] + badd1;
            *(float2*)&Cm[(size_t)r0 * CC + c0]       = v0;
            *(float2*)&Cm[(size_t)(r0 + 8) * CC + c0] = v1;
        }
    }
#undef ISSUE_TILE
}

// ---------------- focusing feature map (in place, one block per row) -----
__global__ __launch_bounds__(256) void process_kernel(float* __restrict__ t) {
    const int r = blockIdx.x;
    float* row = t + (size_t)r * CC;
    const int tid = threadIdx.x;
    __shared__ float red2[256];
    __shared__ float red6[256];

    float v[3];
    float s2 = 0.f, s6 = 0.f;
#pragma unroll
    for (int i = 0; i < 3; i++) {
        int c = tid + i * 256;
        float x = fmaxf(row[c], 0.f) + 1e-6f;
        x = x / g_sp[c];
        v[i] = x;
        float x2 = x * x;
        s2 += x2;
        s6 += x2 * x2 * x2;
    }
    red2[tid] = s2; red6[tid] = s6;
    __syncthreads();
    for (int s = 128; s > 0; s >>= 1) {
        if (tid < s) { red2[tid] += red2[tid + s]; red6[tid] += red6[tid + s]; }
        __syncthreads();
    }
    float nrm  = sqrtf(red2[0]);
    float nrm3 = sqrtf(red6[0]);
    float sc = nrm / nrm3;
#pragma unroll
    for (int i = 0; i < 3; i++) {
        int c = tid + i * 256;
        float x = v[i];
        row[c] = x * x * x * sc;
    }
}

// ---------------- k mean over Nm ----------------
__global__ void kmean_part_kernel() {
    int chunk = blockIdx.x;
    int b = blockIdx.y;
    int c = threadIdx.x;
    float s = 0.f;
    int m0 = chunk * 64;
    for (int m = m0; m < m0 + 64; m++)
        s += g_k[((size_t)m * BB + b) * CC + c];
    g_kmp[(b * 64 + chunk) * CC + c] = s;
}
__global__ void kmean_reduce_kernel() {
    int b = blockIdx.x;
    int c = threadIdx.x;
    float s = 0.f;
    for (int ch = 0; ch < 64; ch++) s += g_kmp[(b * 64 + ch) * CC + c];
    g_km[b * CC + c] = s * (1.f / (float)NM);
}

// ---------------- kv = (1/Nm) k^T v per (b,h) ----------------
__global__ __launch_bounds__(256) void kv_part_kernel() {
    const int bh = blockIdx.x;
    const int chunk = blockIdx.y;
    const int b = bh / HH, head = bh % HH;
    __shared__ float ks[32][64];
    __shared__ float vs[32][64];
    const int tid = threadIdx.x;
    const int i0 = (tid >> 4) * 4;
    const int j0 = (tid & 15) * 4;
    float acc[4][4];
#pragma unroll
    for (int a = 0; a < 4; a++)
#pragma unroll
        for (int c = 0; c < 4; c++) acc[a][c] = 0.f;

    for (int m0 = chunk * 256; m0 < chunk * 256 + 256; m0 += 32) {
#pragma unroll
        for (int l = 0; l < 8; l++) {
            int lin = tid + l * 256;
            int mm = lin >> 6, cc = lin & 63;
            size_t base = ((size_t)(m0 + mm) * BB + b) * CC + head * 64 + cc;
            ks[mm][cc] = g_k[base];
            vs[mm][cc] = g_v[base];
        }
        __syncthreads();
#pragma unroll
        for (int m = 0; m < 32; m++) {
            float a0 = ks[m][i0], a1 = ks[m][i0+1], a2 = ks[m][i0+2], a3 = ks[m][i0+3];
            float b0 = vs[m][j0], b1 = vs[m][j0+1], b2 = vs[m][j0+2], b3 = vs[m][j0+3];
            acc[0][0] += a0*b0; acc[0][1] += a0*b1; acc[0][2] += a0*b2; acc[0][3] += a0*b3;
            acc[1][0] += a1*b0; acc[1][1] += a1*b1; acc[1][2] += a1*b2; acc[1][3] += a1*b3;
            acc[2][0] += a2*b0; acc[2][1] += a2*b1; acc[2][2] += a2*b2; acc[2][3] += a2*b3;
            acc[3][0] += a3*b0; acc[3][1] += a3*b1; acc[3][2] += a3*b2; acc[3][3] += a3*b3;
        }
        __syncthreads();
    }
#pragma unroll
    for (int a = 0; a < 4; a++)
#pragma unroll
        for (int c = 0; c < 4; c++)
            g_kvp[((size_t)(bh * 16 + chunk) * 64 + i0 + a) * 64 + j0 + c] = acc[a][c];
}
__global__ void kv_reduce_kernel() {
    int bh = blockIdx.x;
    int tid = threadIdx.x;
    for (int e = tid; e < 4096; e += 256) {
        float s = 0.f;
        for (int ch = 0; ch < 16; ch++)
            s += g_kvp[((size_t)(bh * 16 + ch)) * 4096 + e];
        g_kv[(size_t)bh * 4096 + e] = s * (1.f / (float)NM);
    }
}

// ---------------- transpose v (m,b,c) -> planes (b,c,m) ----------------
__global__ void transpose_to_planes_kernel() {
    __shared__ float tile[32][33];
    int m0 = blockIdx.x * 32, c0 = blockIdx.y * 32, b = blockIdx.z;
    int lx = threadIdx.x, ly = threadIdx.y;
#pragma unroll
    for (int i = 0; i < 32; i += 8)
        tile[ly + i][lx] = g_v[((size_t)(m0 + ly + i) * BB + b) * CC + c0 + lx];
    __syncthreads();
#pragma unroll
    for (int i = 0; i < 32; i += 8)
        g_vT[((size_t)(b * CC + c0 + ly + i)) * NM + m0 + lx] = tile[lx][ly + i];
}

// ---------------- depthwise 5x5 conv over (16, 256) grid ----------------
__global__ __launch_bounds__(256) void dwconv_kernel(
    const float* __restrict__ w, const float* __restrict__ bias)
{
    const int c = blockIdx.x;
    const int b = blockIdx.y;
    const int dd = c & 63;
    __shared__ float plane[16][260];
    __shared__ float wk[25];
    const int tid = threadIdx.x;
    if (tid < 25) wk[tid] = w[dd * 25 + tid];
    size_t base = ((size_t)(b * CC + c)) * NM;
#pragma unroll
    for (int r = 0; r < 16; r++)
        plane[r][tid + 2] = g_vT[base + r * 256 + tid];
    if (tid < 16) {
        plane[tid][0] = 0.f; plane[tid][1] = 0.f;
        plane[tid][258] = 0.f; plane[tid][259] = 0.f;
    }
    __syncthreads();
    float bv = bias[dd];
#pragma unroll
    for (int r = 0; r < 16; r++) {
        float acc = bv;
#pragma unroll
        for (int dr = -2; dr <= 2; dr++) {
            int rr = r + dr;
            if (rr < 0 || rr > 15) continue;
            const float* pr = &plane[rr][tid];
            const float* wr = &wk[(dr + 2) * 5];
            acc += wr[0]*pr[0] + wr[1]*pr[1] + wr[2]*pr[2] + wr[3]*pr[3] + wr[4]*pr[4];
        }
        g_dT[base + r * 256 + tid] = acc;
    }
}

// ---------------- transpose planes (b,c,m) -> (b,m,c) ----------------
__global__ void transpose_from_planes_kernel() {
    __shared__ float tile[32][33];
    int m0 = blockIdx.x * 32, c0 = blockIdx.y * 32, b = blockIdx.z;
    int lx = threadIdx.x, ly = threadIdx.y;
#pragma unroll
    for (int i = 0; i < 32; i += 8)
        tile[ly + i][lx] = g_dT[((size_t)(b * CC + c0 + ly + i)) * NM + m0 + lx];
    __syncthreads();
#pragma unroll
    for (int i = 0; i < 32; i += 8)
        g_dwc[((size_t)(b * NM + m0 + ly + i)) * CC + c0 + lx] = tile[lx][ly + i];
}

// ---------------- attention epilogue: out_pre = z*(q@kv) + dwc ----------
// Stores tf32-rounded AND K-permuted (slot = (k%4)*8 + k/4 within each
// 32-col block) so proj GEMM loads fragments as float4 with no cvt.
__global__ __launch_bounds__(256) void attn_epilogue_kernel(
    float* __restrict__ out_pre)
{
    const int chunk = blockIdx.x;
    const int head  = blockIdx.y;
    const int b     = blockIdx.z;
    const int n0 = chunk * 64;
    __shared__ float qs[64][64];
    __shared__ float kvs[64][64];
    __shared__ float kms[64];
    __shared__ float zs[64];
    const int tid = threadIdx.x;

    const size_t kvbase = ((size_t)(b * HH + head)) * 4096;
#pragma unroll
    for (int l = 0; l < 16; l++) {
        int lin = tid + l * 256;
        kvs[lin >> 6][lin & 63] = g_kv[kvbase + lin];
    }
    if (tid < 64) kms[tid] = g_km[b * CC + head * 64 + tid];
#pragma unroll
    for (int l = 0; l < 16; l++) {
        int lin = tid + l * 256;
        int row = lin >> 6, i = lin & 63;
        qs[row][i] = g_q[((size_t)((n0 + row) * BB + b)) * CC + head * 64 + i];
    }
    __syncthreads();
    if (tid < 64) {
        float s = 0.f;
#pragma unroll
        for (int i = 0; i < 64; i++) s += qs[tid][i] * kms[i];
        zs[tid] = 1.f / (s + 1e-6f);
    }
    __syncthreads();

    const int colg = (tid & 15) * 4;
    const int rowg = (tid >> 4) * 4;
    float acc[4][4];
#pragma unroll
    for (int a = 0; a < 4; a++)
#pragma unroll
        for (int c = 0; c < 4; c++) acc[a][c] = 0.f;

#pragma unroll 8
    for (int i = 0; i < 64; i++) {
        float4 bv = *(const float4*)&kvs[i][colg];
#pragma unroll
        for (int j = 0; j < 4; j++) {
            float a = qs[rowg + j][i];
            acc[j][0] += a * bv.x; acc[j][1] += a * bv.y;
            acc[j][2] += a * bv.z; acc[j][3] += a * bv.w;
        }
    }
    // permuted store: global col = head*64 + colg + jj; within its 32-block
    // (k = (colg+jj)%32), slot = jj*8 + (colg%32)/4  (colg%4==0).
    const int blk   = head * 64 + (colg & 32);      // 32-block base col
    const int soff  = (colg & 31) >> 2;             // slot offset
#pragma unroll
    for (int j = 0; j < 4; j++) {
        int n = n0 + rowg + j;
        int m = n & (NM - 1);
        float z = zs[rowg + j];
        size_t orow = ((size_t)(n * BB + b)) * CC;
        const float* dvp = &g_dwc[((size_t)(b * NM + m)) * CC + head * 64 + colg];
#pragma unroll
        for (int jj = 0; jj < 4; jj++) {
            float val = acc[j][jj] * z + dvp[jj];
            out_pre[orow + blk + jj * 8 + soff] =
                __uint_as_float(cvt_tf32(val));
        }
    }
}

// ---------------- launch ----------------
extern "C" void kernel_launch(void* const* d_in, const int* in_sizes, int n_in,
                              void* d_out, int out_size) {
    const float* x     = (const float*)d_in[0];
    const float* mem   = (const float*)d_in[1];
    const float* w_q   = (const float*)d_in[2];
    const float* w_k   = (const float*)d_in[3];
    const float* w_v   = (const float*)d_in[4];
    const float* w_p   = (const float*)d_in[5];
    const float* b_p   = (const float*)d_in[6];
    const float* dwc_w = (const float*)d_in[7];
    const float* dwc_b = (const float*)d_in[8];
    const float* scale = (const float*)d_in[9];
    float* out = (float*)d_out;

    float *pq, *pk, *pv, *pop, *pmr, *pwvr, *pwpr;
    cudaGetSymbolAddress((void**)&pq,   g_q);
    cudaGetSymbolAddress((void**)&pk,   g_k);
    cudaGetSymbolAddress((void**)&pv,   g_v);
    cudaGetSymbolAddress((void**)&pop,  g_op);
    cudaGetSymbolAddress((void**)&pmr,  g_mr);
    cudaGetSymbolAddress((void**)&pwvr, g_wvr);
    cudaGetSymbolAddress((void**)&pwpr, g_wpr);

    __nv_bfloat16 *xh, *xl, *mh, *ml, *wqh, *wql, *wkh, *wkl;
    cudaGetSymbolAddress((void**)&xh,  g_xh);  cudaGetSymbolAddress((void**)&xl,  g_xl);
    cudaGetSymbolAddress((void**)&mh,  g_mh);  cudaGetSymbolAddress((void**)&ml,  g_ml);
    cudaGetSymbolAddress((void**)&wqh, g_wqh); cudaGetSymbolAddress((void**)&wql, g_wql);
    cudaGetSymbolAddress((void**)&wkh, g_wkh); cudaGetSymbolAddress((void**)&wkl, g_wkl);

    cudaFuncSetAttribute(tgemm_bf16_3t,
                         cudaFuncAttributeMaxDynamicSharedMemorySize, BSMEM);
    cudaFuncSetAttribute(tgemm_tf32<false>,
                         cudaFuncAttributeMaxDynamicSharedMemorySize, GSMEM_BYTES);
    cudaFuncSetAttribute(tgemm_tf32<true>,
                         cudaFuncAttributeMaxDynamicSharedMemorySize, GSMEM_BYTES);

    sp_kernel<<<1, CC>>>(scale);

    const int NW4 = CC * CC / 4;
    split_kernel<<<(RQ * CC / 4 + 255) / 256, 256>>>(x,   xh, xl, RQ * CC / 4);
    split_kernel<<<(RM * CC / 4 + 255) / 256, 256>>>(mem, mh, ml, RM * CC / 4);
    split_kernel<<<(NW4 + 255) / 256, 256>>>(w_q, wqh, wql, NW4);
    split_kernel<<<(NW4 + 255) / 256, 256>>>(w_k, wkh, wkl, NW4);
    round_perm_kernel<<<(RM * CC / 4 + 255) / 256, 256>>>(mem, pmr, RM * CC / 4);
    round_perm_kernel<<<(NW4 + 255) / 256, 256>>>(w_v, pwvr, NW4);
    round_perm_kernel<<<(NW4 + 255) / 256, 256>>>(w_p, pwpr, NW4);

    // q,k: bf16 3-term split
    tgemm_bf16_3t<<<dim3(RQ / 128, CC / 128), 256, BSMEM>>>(xh, xl, wqh, wql, pq);
    tgemm_bf16_3t<<<dim3(RM / 128, CC / 128), 256, BSMEM>>>(mh, ml, wkh, wkl, pk);
    // v: tf32 on pre-rounded+permuted operands
    tgemm_tf32<false><<<dim3(RM / 128, CC / 128), 256, GSMEM_BYTES>>>(pmr, pwvr, nullptr, pv, RM);

    process_kernel<<<RQ, 256>>>(pq);
    process_kernel<<<RM, 256>>>(pk);

    kmean_part_kernel<<<dim3(64, BB), CC>>>();
    kmean_reduce_kernel<<<BB, CC>>>();

    kv_part_kernel<<<dim3(BB * HH, 16), 256>>>();
    kv_reduce_kernel<<<BB * HH, 256>>>();

    transpose_to_planes_kernel<<<dim3(NM / 32, CC / 32, BB), dim3(32, 8)>>>();
    dwconv_kernel<<<dim3(CC, BB), 256>>>(dwc_w, dwc_b);
    transpose_from_planes_kernel<<<dim3(NM / 32, CC / 32, BB), dim3(32, 8)>>>();

    attn_epilogue_kernel<<<dim3(NX / 64, HH, BB), 256>>>(pop);

    // proj: tf32 on pre-rounded+permuted operands
    tgemm_tf32<true><<<dim3(RQ / 128, CC / 128), 256, GSMEM_BYTES>>>(pop, pwpr, b_p, out, RQ);
}

// round 15
// speedup vs baseline: 1.0184x; 1.0184x over previous
#include <cuda_runtime.h>
#include <cuda_bf16.h>
#include <math.h>
#include <stdint.h>

// Fixed problem shapes
#define CC   768
#define BB   2
#define HH   12
#define DDIM 64
#define NM   4096
#define NX   16384
#define RQ   (NX*BB)   // 32768 rows of x
#define RM   (NM*BB)   // 8192 rows of memory

// ---------------- scratch (device globals; no allocation) ----------------
__device__ float g_q  [RQ*CC];
__device__ float g_k  [RM*CC];
__device__ float g_v  [RM*CC];
__device__ float g_sp [CC];
__device__ float g_kmp[BB*64*CC];
__device__ float g_km [BB*CC];
__device__ float g_kvp[BB*HH*16*DDIM*DDIM];
__device__ float g_kv [BB*HH*DDIM*DDIM];
__device__ float g_vT [BB*CC*NM];
__device__ float g_dT [BB*CC*NM];
__device__ float g_dwc[BB*NM*CC];
__device__ float g_op [RQ*CC];    // out_pre, tf32-rounded at store

// pre-rounded tf32 operands (fp32 with RNA-truncated mantissa)
__device__ float g_mr [RM*CC];
__device__ float g_wvr[CC*CC];
__device__ float g_wpr[CC*CC];

// bf16 hi/lo split planes (16B-aligned for cp.async)
__device__ __align__(128) __nv_bfloat16 g_xh[RQ*CC],  g_xl[RQ*CC];
__device__ __align__(128) __nv_bfloat16 g_mh[RM*CC],  g_ml[RM*CC];
__device__ __align__(128) __nv_bfloat16 g_wqh[CC*CC], g_wql[CC*CC];
__device__ __align__(128) __nv_bfloat16 g_wkh[CC*CC], g_wkl[CC*CC];

__device__ __forceinline__ uint32_t cvt_tf32(float x) {
    uint32_t r;
    asm("cvt.rna.tf32.f32 %0, %1;" : "=r"(r) : "f"(x));
    return r;
}

// ---------------- softplus of scale ----------------
__global__ void sp_kernel(const float* __restrict__ scale) {
    int i = threadIdx.x;
    float s = scale[i];
    g_sp[i] = (s > 20.f) ? s : log1pf(expf(s));
}

// ---------------- fp32 -> bf16 hi/lo split ----------------
__global__ void split_kernel(const float* __restrict__ src,
                             __nv_bfloat16* __restrict__ hi,
                             __nv_bfloat16* __restrict__ lo, int n4) {
    int i = blockIdx.x * 256 + threadIdx.x;
    if (i >= n4) return;
    float4 v = ((const float4*)src)[i];
    __nv_bfloat16 h0 = __float2bfloat16(v.x);
    __nv_bfloat16 h1 = __float2bfloat16(v.y);
    __nv_bfloat16 h2 = __float2bfloat16(v.z);
    __nv_bfloat16 h3 = __float2bfloat16(v.w);
    __nv_bfloat16 l0 = __float2bfloat16(v.x - __bfloat162float(h0));
    __nv_bfloat16 l1 = __float2bfloat16(v.y - __bfloat162float(h1));
    __nv_bfloat16 l2 = __float2bfloat16(v.z - __bfloat162float(h2));
    __nv_bfloat16 l3 = __float2bfloat16(v.w - __bfloat162float(h3));
    __nv_bfloat162 H0; H0.x = h0; H0.y = h1;
    __nv_bfloat162 H1; H1.x = h2; H1.y = h3;
    __nv_bfloat162 L0; L0.x = l0; L0.y = l1;
    __nv_bfloat162 L1; L1.x = l2; L1.y = l3;
    ((__nv_bfloat162*)hi)[2*i]   = H0;
    ((__nv_bfloat162*)hi)[2*i+1] = H1;
    ((__nv_bfloat162*)lo)[2*i]   = L0;
    ((__nv_bfloat162*)lo)[2*i+1] = L1;
}

// ---------------- fp32 -> RNA tf32-rounded fp32 ----------------
__global__ void round_tf32_kernel(const float* __restrict__ src,
                                  float* __restrict__ dst, int n4) {
    int i = blockIdx.x * 256 + threadIdx.x;
    if (i >= n4) return;
    float4 v = ((const float4*)src)[i];
    float4 o;
    o.x = __uint_as_float(cvt_tf32(v.x));
    o.y = __uint_as_float(cvt_tf32(v.y));
    o.z = __uint_as_float(cvt_tf32(v.z));
    o.w = __uint_as_float(cvt_tf32(v.w));
    ((float4*)dst)[i] = o;
}

// =====================================================================
// bf16 3-term GEMM (m16n8k16): C = Ah*Bh + Ah*Bl + Al*Bh, fp32 accum.
// CTA 128x128, 128 threads, 4 warps with 64x64 warp tiles (2x2 grid):
// halves smem fragment traffic per FLOP vs 64x32 tiles (smem-BW bound).
// ldmatrix.x4 loads, term-major MMA ordering, single-sync pipeline.
// =====================================================================
#define BROW  80
#define BPL   (128*BROW)
#define BSTG  (4*BPL)
#define BSMEM (2*BSTG)

__device__ __forceinline__ void ldm_x4(uint32_t* r, uint32_t addr) {
    asm volatile("ldmatrix.sync.aligned.m8n8.x4.shared.b16 {%0,%1,%2,%3}, [%4];"
                 : "=r"(r[0]), "=r"(r[1]), "=r"(r[2]), "=r"(r[3]) : "r"(addr));
}

__global__ void __launch_bounds__(128) tgemm_bf16_3t(
    const __nv_bfloat16* __restrict__ Ah, const __nv_bfloat16* __restrict__ Al,
    const __nv_bfloat16* __restrict__ Bh, const __nv_bfloat16* __restrict__ Bl,
    float* __restrict__ Cm)
{
    extern __shared__ __align__(128) char bsm[];
    const uint32_t sbase = (uint32_t)__cvta_generic_to_shared(bsm);
    const int tid  = threadIdx.x;
    const int lane = tid & 31;
    const int warp = tid >> 5;          // 0..3
    const int wm = (warp & 1) * 64;
    const int wn = (warp >> 1) * 64;
    const int lr = lane >> 2;
    const int lc = lane & 3;
    const int bm = blockIdx.x * 128;
    const int bn = blockIdx.y * 128;

    const int a_row = lane & 15;
    const int a_ko  = (lane >> 4) * 16;
    const int b_row = (lane & 7) + ((lane >> 4) & 1) * 8;
    const int b_ko  = ((lane >> 3) & 1) * 16;

    float acc[4][8][4];
#pragma unroll
    for (int mt = 0; mt < 4; mt++)
#pragma unroll
        for (int nt = 0; nt < 8; nt++)
#pragma unroll
            for (int e = 0; e < 4; e++) acc[mt][nt][e] = 0.f;

    const int NITER = CC / 32;   // 24

#define BISSUE(IT, BUFI)                                                          \
    do {                                                                           \
        int _k0 = (IT) * 32;                                                       \
        char* _st = bsm + (BUFI) * BSTG;                                           \
        _Pragma("unroll")                                                          \
        for (int _j = 0; _j < 16; _j++) {                                          \
            int _u = tid + 128 * _j;       /* 0..2047 */                           \
            int _seg = _u & 3, _row = (_u >> 2) & 127, _pl = _u >> 9;              \
            const __nv_bfloat16* _src = (_pl == 0) ? Ah : (_pl == 1) ? Al          \
                                        : (_pl == 2) ? Bh : Bl;                    \
            int _r0 = (_pl < 2) ? bm : bn;                                         \
            uint32_t _d = (uint32_t)__cvta_generic_to_shared(                      \
                _st + _pl * BPL + _row * BROW + _seg * 16);                        \
            asm volatile("cp.async.cg.shared.global [%0], [%1], 16;" ::            \
                         "r"(_d),                                                  \
                         "l"(_src + (size_t)(_r0 + _row) * CC + _k0 + _seg * 8));  \
        }                                                                          \
        asm volatile("cp.async.commit_group;");                                    \
    } while (0)

    int buf = 0;
    BISSUE(0, 0);

    for (int it = 0; it < NITER; ++it) {
        asm volatile("cp.async.wait_group 0;");
        __syncthreads();
        if (it + 1 < NITER) BISSUE(it + 1, buf ^ 1);

        const uint32_t sAh = sbase + buf * BSTG;
        const uint32_t sAl = sAh + BPL;
        const uint32_t sBh = sAh + 2 * BPL;
        const uint32_t sBl = sAh + 3 * BPL;

#pragma unroll
        for (int ks = 0; ks < 2; ks++) {
            const int kbase = ks * 32;
            uint32_t ah[4][4], al[4][4];
#pragma unroll
            for (int mt = 0; mt < 4; mt++) {
                uint32_t off = (uint32_t)((wm + mt * 16 + a_row) * BROW + kbase + a_ko);
                ldm_x4(ah[mt], sAh + off);
                ldm_x4(al[mt], sAl + off);
            }
            // B in two halves of 4 n8-tiles to bound live registers
#pragma unroll
            for (int half = 0; half < 2; half++) {
                uint32_t bh[4][2], bl[4][2];
#pragma unroll
                for (int ntp = 0; ntp < 2; ntp++) {
                    int ntp2 = half * 2 + ntp;
                    uint32_t off = (uint32_t)((wn + ntp2 * 16 + b_row) * BROW + kbase + b_ko);
                    uint32_t th[4], tl[4];
                    ldm_x4(th, sBh + off);
                    ldm_x4(tl, sBl + off);
                    bh[ntp*2][0]   = th[0]; bh[ntp*2][1]   = th[1];
                    bh[ntp*2+1][0] = th[2]; bh[ntp*2+1][1] = th[3];
                    bl[ntp*2][0]   = tl[0]; bl[ntp*2][1]   = tl[1];
                    bl[ntp*2+1][0] = tl[2]; bl[ntp*2+1][1] = tl[3];
                }
#define BMMA(AF, BF, mt, ntl)                                                 \
    asm volatile(                                                             \
        "mma.sync.aligned.m16n8k16.row.col.f32.bf16.bf16.f32 "                \
        "{%0,%1,%2,%3}, {%4,%5,%6,%7}, {%8,%9}, {%0,%1,%2,%3};"               \
        : "+f"(acc[mt][half*4+ntl][0]), "+f"(acc[mt][half*4+ntl][1]),         \
          "+f"(acc[mt][half*4+ntl][2]), "+f"(acc[mt][half*4+ntl][3])          \
        : "r"(AF[mt][0]), "r"(AF[mt][1]), "r"(AF[mt][2]), "r"(AF[mt][3]),     \
          "r"(BF[ntl][0]), "r"(BF[ntl][1]))
                // term-major: 16 independent MMAs per term
#pragma unroll
                for (int mt = 0; mt < 4; mt++)
#pragma unroll
                    for (int ntl = 0; ntl < 4; ntl++) BMMA(ah, bh, mt, ntl);
#pragma unroll
                for (int mt = 0; mt < 4; mt++)
#pragma unroll
                    for (int ntl = 0; ntl < 4; ntl++) BMMA(ah, bl, mt, ntl);
#pragma unroll
                for (int mt = 0; mt < 4; mt++)
#pragma unroll
                    for (int ntl = 0; ntl < 4; ntl++) BMMA(al, bh, mt, ntl);
#undef BMMA
            }
        }
        buf ^= 1;
    }

#pragma unroll
    for (int mt = 0; mt < 4; mt++) {
#pragma unroll
        for (int nt = 0; nt < 8; nt++) {
            int r0 = bm + wm + mt * 16 + lr;
            int c0 = bn + wn + nt * 8 + 2 * lc;
            float2 v0, v1;
            v0.x = acc[mt][nt][0]; v0.y = acc[mt][nt][1];
            v1.x = acc[mt][nt][2]; v1.y = acc[mt][nt][3];
            *(float2*)&Cm[(size_t)r0 * CC + c0]       = v0;
            *(float2*)&Cm[(size_t)(r0 + 8) * CC + c0] = v1;
        }
    }
#undef BISSUE
}

// =====================================================================
// TF32 GEMM for v/proj on pre-rounded operands (no inline cvt).
// CTA 128x128, 128 threads, 4 warps with 64x64 warp tiles.
// =====================================================================
#define GSTRIDE 36
#define GBUF    (128*GSTRIDE)
#define GSMEM_BYTES (4 * GBUF * 2 * 2)

template <bool ADD_BIAS>
__global__ void __launch_bounds__(128) tgemm_tf32(
    const float* __restrict__ A, const float* __restrict__ W,
    const float* __restrict__ bias, float* __restrict__ Cm, int M)
{
    extern __shared__ float smem[];
    float* As = smem;
    float* Bs = smem + 2 * GBUF;

    const int tid  = threadIdx.x;
    const int lane = tid & 31;
    const int warp = tid >> 5;          // 0..3
    const int wm = (warp & 1) * 64;
    const int wn = (warp >> 1) * 64;
    const int lr = lane >> 2;
    const int lc = lane & 3;
    const int bm = blockIdx.x * 128;
    const int bn = blockIdx.y * 128;

    float acc[4][8][4];
#pragma unroll
    for (int mt = 0; mt < 4; mt++)
#pragma unroll
        for (int nt = 0; nt < 8; nt++)
#pragma unroll
            for (int e = 0; e < 4; e++) acc[mt][nt][e] = 0.f;

    const int NITER = CC / 32;

#define ISSUE_TILE(IT, BUFI)                                                     \
    do {                                                                          \
        int _k0 = (IT) * 32;                                                      \
        float* _dA = As + (BUFI) * GBUF;                                          \
        float* _dB = Bs + (BUFI) * GBUF;                                          \
        _Pragma("unroll")                                                         \
        for (int _l = 0; _l < 8; _l++) {                                          \
            int _lin = tid + _l * 128;                                            \
            int _m = _lin >> 3, _kq = (_lin & 7) << 2;                            \
            uint32_t _da = (uint32_t)__cvta_generic_to_shared(                    \
                _dA + _m * GSTRIDE + _kq);                                        \
            asm volatile("cp.async.cg.shared.global [%0], [%1], 16;" ::           \
                         "r"(_da),                                                \
                         "l"(A + (size_t)(bm + _m) * CC + _k0 + _kq));            \
            uint32_t _db = (uint32_t)__cvta_generic_to_shared(                    \
                _dB + _m * GSTRIDE + _kq);                                        \
            asm volatile("cp.async.cg.shared.global [%0], [%1], 16;" ::           \
                         "r"(_db),                                                \
                         "l"(W + (size_t)(bn + _m) * CC + _k0 + _kq));            \
        }                                                                         \
        asm volatile("cp.async.commit_group;");                                   \
    } while (0)

    int buf = 0;
    ISSUE_TILE(0, 0);

    for (int it = 0; it < NITER; ++it) {
        asm volatile("cp.async.wait_group 0;");
        __syncthreads();
        if (it + 1 < NITER) ISSUE_TILE(it + 1, buf ^ 1);

        const float* cA = As + buf * GBUF;
        const float* cB = Bs + buf * GBUF;

#pragma unroll
        for (int ks = 0; ks < 4; ks++) {
            const int kk = ks * 8;
            uint32_t ah[4][4];
#pragma unroll
            for (int mt = 0; mt < 4; mt++) {
                const float* p0 = cA + (wm + mt * 16 + lr) * GSTRIDE + kk + lc;
                const float* p1 = cA + (wm + mt * 16 + lr + 8) * GSTRIDE + kk + lc;
                ah[mt][0] = __float_as_uint(p0[0]);
                ah[mt][1] = __float_as_uint(p1[0]);
                ah[mt][2] = __float_as_uint(p0[4]);
                ah[mt][3] = __float_as_uint(p1[4]);
            }
#pragma unroll
            for (int half = 0; half < 2; half++) {
                uint32_t bh[4][2];
#pragma unroll
                for (int ntl = 0; ntl < 4; ntl++) {
                    int nt = half * 4 + ntl;
                    const float* pb = cB + (wn + nt * 8 + lr) * GSTRIDE + kk + lc;
                    bh[ntl][0] = __float_as_uint(pb[0]);
                    bh[ntl][1] = __float_as_uint(pb[4]);
                }
#pragma unroll
                for (int mt = 0; mt < 4; mt++)
#pragma unroll
                    for (int ntl = 0; ntl < 4; ntl++) {
                        asm volatile(
                            "mma.sync.aligned.m16n8k8.row.col.f32.tf32.tf32.f32 "
                            "{%0,%1,%2,%3}, {%4,%5,%6,%7}, {%8,%9}, {%0,%1,%2,%3};"
                            : "+f"(acc[mt][half*4+ntl][0]), "+f"(acc[mt][half*4+ntl][1]),
                              "+f"(acc[mt][half*4+ntl][2]), "+f"(acc[mt][half*4+ntl][3])
                            : "r"(ah[mt][0]), "r"(ah[mt][1]),
                              "r"(ah[mt][2]), "r"(ah[mt][3]),
                              "r"(bh[ntl][0]), "r"(bh[ntl][1]));
                    }
            }
        }
        buf ^= 1;
    }

#pragma unroll
    for (int mt = 0; mt < 4; mt++) {
#pragma unroll
        for (int nt = 0; nt < 8; nt++) {
            int r0 = bm + wm + mt * 16 + lr;
            int c0 = bn + wn + nt * 8 + 2 * lc;
            float badd0 = 0.f, badd1 = 0.f;
            if (ADD_BIAS) { badd0 = bias[c0]; badd1 = bias[c0 + 1]; }
            float2 v0, v1;
            v0.x = acc[mt][nt][0] + badd0; v0.y = acc[mt][nt][1] + badd1;
            v1.x = acc[mt][nt][2] + badd0; v1.y = acc[mt][nt][3] + badd1;
            *(float2*)&Cm[(size_t)r0 * CC + c0]       = v0;
            *(float2*)&Cm[(size_t)(r0 + 8) * CC + c0] = v1;
        }
    }
#undef ISSUE_TILE
}

// ---------------- focusing feature map (in place, one block per row) -----
__global__ __launch_bounds__(256) void process_kernel(float* __restrict__ t) {
    const int r = blockIdx.x;
    float* row = t + (size_t)r * CC;
    const int tid = threadIdx.x;
    __shared__ float red2[256];
    __shared__ float red6[256];

    float v[3];
    float s2 = 0.f, s6 = 0.f;
#pragma unroll
    for (int i = 0; i < 3; i++) {
        int c = tid + i * 256;
        float x = fmaxf(row[c], 0.f) + 1e-6f;
        x = x / g_sp[c];
        v[i] = x;
        float x2 = x * x;
        s2 += x2;
        s6 += x2 * x2 * x2;
    }
    red2[tid] = s2; red6[tid] = s6;
    __syncthreads();
    for (int s = 128; s > 0; s >>= 1) {
        if (tid < s) { red2[tid] += red2[tid + s]; red6[tid] += red6[tid + s]; }
        __syncthreads();
    }
    float nrm  = sqrtf(red2[0]);
    float nrm3 = sqrtf(red6[0]);
    float sc = nrm / nrm3;
#pragma unroll
    for (int i = 0; i < 3; i++) {
        int c = tid + i * 256;
        float x = v[i];
        row[c] = x * x * x * sc;
    }
}

// ---------------- k mean over Nm ----------------
__global__ void kmean_part_kernel() {
    int chunk = blockIdx.x;
    int b = blockIdx.y;
    int c = threadIdx.x;
    float s = 0.f;
    int m0 = chunk * 64;
    for (int m = m0; m < m0 + 64; m++)
        s += g_k[((size_t)m * BB + b) * CC + c];
    g_kmp[(b * 64 + chunk) * CC + c] = s;
}
__global__ void kmean_reduce_kernel() {
    int b = blockIdx.x;
    int c = threadIdx.x;
    float s = 0.f;
    for (int ch = 0; ch < 64; ch++) s += g_kmp[(b * 64 + ch) * CC + c];
    g_km[b * CC + c] = s * (1.f / (float)NM);
}

// ---------------- kv = (1/Nm) k^T v per (b,h) ----------------
__global__ __launch_bounds__(256) void kv_part_kernel() {
    const int bh = blockIdx.x;
    const int chunk = blockIdx.y;
    const int b = bh / HH, head = bh % HH;
    __shared__ float ks[32][64];
    __shared__ float vs[32][64];
    const int tid = threadIdx.x;
    const int i0 = (tid >> 4) * 4;
    const int j0 = (tid & 15) * 4;
    float acc[4][4];
#pragma unroll
    for (int a = 0; a < 4; a++)
#pragma unroll
        for (int c = 0; c < 4; c++) acc[a][c] = 0.f;

    for (int m0 = chunk * 256; m0 < chunk * 256 + 256; m0 += 32) {
#pragma unroll
        for (int l = 0; l < 8; l++) {
            int lin = tid + l * 256;
            int mm = lin >> 6, cc = lin & 63;
            size_t base = ((size_t)(m0 + mm) * BB + b) * CC + head * 64 + cc;
            ks[mm][cc] = g_k[base];
            vs[mm][cc] = g_v[base];
        }
        __syncthreads();
#pragma unroll
        for (int m = 0; m < 32; m++) {
            float a0 = ks[m][i0], a1 = ks[m][i0+1], a2 = ks[m][i0+2], a3 = ks[m][i0+3];
            float b0 = vs[m][j0], b1 = vs[m][j0+1], b2 = vs[m][j0+2], b3 = vs[m][j0+3];
            acc[0][0] += a0*b0; acc[0][1] += a0*b1; acc[0][2] += a0*b2; acc[0][3] += a0*b3;
            acc[1][0] += a1*b0; acc[1][1] += a1*b1; acc[1][2] += a1*b2; acc[1][3] += a1*b3;
            acc[2][0] += a2*b0; acc[2][1] += a2*b1; acc[2][2] += a2*b2; acc[2][3] += a2*b3;
            acc[3][0] += a3*b0; acc[3][1] += a3*b1; acc[3][2] += a3*b2; acc[3][3] += a3*b3;
        }
        __syncthreads();
    }
#pragma unroll
    for (int a = 0; a < 4; a++)
#pragma unroll
        for (int c = 0; c < 4; c++)
            g_kvp[((size_t)(bh * 16 + chunk) * 64 + i0 + a) * 64 + j0 + c] = acc[a][c];
}
__global__ void kv_reduce_kernel() {
    int bh = blockIdx.x;
    int tid = threadIdx.x;
    for (int e = tid; e < 4096; e += 256) {
        float s = 0.f;
        for (int ch = 0; ch < 16; ch++)
            s += g_kvp[((size_t)(bh * 16 + ch)) * 4096 + e];
        g_kv[(size_t)bh * 4096 + e] = s * (1.f / (float)NM);
    }
}

// ---------------- transpose v (m,b,c) -> planes (b,c,m) ----------------
__global__ void transpose_to_planes_kernel() {
    __shared__ float tile[32][33];
    int m0 = blockIdx.x * 32, c0 = blockIdx.y * 32, b = blockIdx.z;
    int lx = threadIdx.x, ly = threadIdx.y;
#pragma unroll
    for (int i = 0; i < 32; i += 8)
        tile[ly + i][lx] = g_v[((size_t)(m0 + ly + i) * BB + b) * CC + c0 + lx];
    __syncthreads();
#pragma unroll
    for (int i = 0; i < 32; i += 8)
        g_vT[((size_t)(b * CC + c0 + ly + i)) * NM + m0 + lx] = tile[lx][ly + i];
}

// ---------------- depthwise 5x5 conv over (16, 256) grid ----------------
__global__ __launch_bounds__(256) void dwconv_kernel(
    const float* __restrict__ w, const float* __restrict__ bias)
{
    const int c = blockIdx.x;
    const int b = blockIdx.y;
    const int dd = c & 63;
    __shared__ float plane[16][260];
    __shared__ float wk[25];
    const int tid = threadIdx.x;
    if (tid < 25) wk[tid] = w[dd * 25 + tid];
    size_t base = ((size_t)(b * CC + c)) * NM;
#pragma unroll
    for (int r = 0; r < 16; r++)
        plane[r][tid + 2] = g_vT[base + r * 256 + tid];
    if (tid < 16) {
        plane[tid][0] = 0.f; plane[tid][1] = 0.f;
        plane[tid][258] = 0.f; plane[tid][259] = 0.f;
    }
    __syncthreads();
    float bv = bias[dd];
#pragma unroll
    for (int r = 0; r < 16; r++) {
        float acc = bv;
#pragma unroll
        for (int dr = -2; dr <= 2; dr++) {
            int rr = r + dr;
            if (rr < 0 || rr > 15) continue;
            const float* pr = &plane[rr][tid];
            const float* wr = &wk[(dr + 2) * 5];
            acc += wr[0]*pr[0] + wr[1]*pr[1] + wr[2]*pr[2] + wr[3]*pr[3] + wr[4]*pr[4];
        }
        g_dT[base + r * 256 + tid] = acc;
    }
}

// ---------------- transpose planes (b,c,m) -> (b,m,c) ----------------
__global__ void transpose_from_planes_kernel() {
    __shared__ float tile[32][33];
    int m0 = blockIdx.x * 32, c0 = blockIdx.y * 32, b = blockIdx.z;
    int lx = threadIdx.x, ly = threadIdx.y;
#pragma unroll
    for (int i = 0; i < 32; i += 8)
        tile[ly + i][lx] = g_dT[((size_t)(b * CC + c0 + ly + i)) * NM + m0 + lx];
    __syncthreads();
#pragma unroll
    for (int i = 0; i < 32; i += 8)
        g_dwc[((size_t)(b * NM + m0 + ly + i)) * CC + c0 + lx] = tile[lx][ly + i];
}

// ---------------- attention epilogue: out_pre = z*(q@kv) + dwc ----------
// Output rounded to tf32-representable fp32 (RNA) so proj skips inline cvt.
__global__ __launch_bounds__(256) void attn_epilogue_kernel(
    float* __restrict__ out_pre)
{
    const int chunk = blockIdx.x;
    const int head  = blockIdx.y;
    const int b     = blockIdx.z;
    const int n0 = chunk * 64;
    __shared__ float qs[64][64];
    __shared__ float kvs[64][64];
    __shared__ float kms[64];
    __shared__ float zs[64];
    const int tid = threadIdx.x;

    const size_t kvbase = ((size_t)(b * HH + head)) * 4096;
#pragma unroll
    for (int l = 0; l < 16; l++) {
        int lin = tid + l * 256;
        kvs[lin >> 6][lin & 63] = g_kv[kvbase + lin];
    }
    if (tid < 64) kms[tid] = g_km[b * CC + head * 64 + tid];
#pragma unroll
    for (int l = 0; l < 16; l++) {
        int lin = tid + l * 256;
        int row = lin >> 6, i = lin & 63;
        qs[row][i] = g_q[((size_t)((n0 + row) * BB + b)) * CC + head * 64 + i];
    }
    __syncthreads();
    if (tid < 64) {
        float s = 0.f;
#pragma unroll
        for (int i = 0; i < 64; i++) s += qs[tid][i] * kms[i];
        zs[tid] = 1.f / (s + 1e-6f);
    }
    __syncthreads();

    const int colg = (tid & 15) * 4;
    const int rowg = (tid >> 4) * 4;
    float acc[4][4];
#pragma unroll
    for (int a = 0; a < 4; a++)
#pragma unroll
        for (int c = 0; c < 4; c++) acc[a][c] = 0.f;

#pragma unroll 8
    for (int i = 0; i < 64; i++) {
        float4 bv = *(const float4*)&kvs[i][colg];
#pragma unroll
        for (int j = 0; j < 4; j++) {
            float a = qs[rowg + j][i];
            acc[j][0] += a * bv.x; acc[j][1] += a * bv.y;
            acc[j][2] += a * bv.z; acc[j][3] += a * bv.w;
        }
    }
#pragma unroll
    for (int j = 0; j < 4; j++) {
        int n = n0 + rowg + j;
        int m = n & (NM - 1);
        float z = zs[rowg + j];
        size_t orow = ((size_t)(n * BB + b)) * CC + head * 64 + colg;
        float4 dv = *(const float4*)&g_dwc[((size_t)(b * NM + m)) * CC + head * 64 + colg];
        float4 o;
        o.x = __uint_as_float(cvt_tf32(acc[j][0] * z + dv.x));
        o.y = __uint_as_float(cvt_tf32(acc[j][1] * z + dv.y));
        o.z = __uint_as_float(cvt_tf32(acc[j][2] * z + dv.z));
        o.w = __uint_as_float(cvt_tf32(acc[j][3] * z + dv.w));
        *(float4*)&out_pre[orow] = o;
    }
}

// ---------------- launch ----------------
extern "C" void kernel_launch(void* const* d_in, const int* in_sizes, int n_in,
                              void* d_out, int out_size) {
    const float* x     = (const float*)d_in[0];
    const float* mem   = (const float*)d_in[1];
    const float* w_q   = (const float*)d_in[2];
    const float* w_k   = (const float*)d_in[3];
    const float* w_v   = (const float*)d_in[4];
    const float* w_p   = (const float*)d_in[5];
    const float* b_p   = (const float*)d_in[6];
    const float* dwc_w = (const float*)d_in[7];
    const float* dwc_b = (const float*)d_in[8];
    const float* scale = (const float*)d_in[9];
    float* out = (float*)d_out;

    float *pq, *pk, *pv, *pop, *pmr, *pwvr, *pwpr;
    cudaGetSymbolAddress((void**)&pq,   g_q);
    cudaGetSymbolAddress((void**)&pk,   g_k);
    cudaGetSymbolAddress((void**)&pv,   g_v);
    cudaGetSymbolAddress((void**)&pop,  g_op);
    cudaGetSymbolAddress((void**)&pmr,  g_mr);
    cudaGetSymbolAddress((void**)&pwvr, g_wvr);
    cudaGetSymbolAddress((void**)&pwpr, g_wpr);

    __nv_bfloat16 *xh, *xl, *mh, *ml, *wqh, *wql, *wkh, *wkl;
    cudaGetSymbolAddress((void**)&xh,  g_xh);  cudaGetSymbolAddress((void**)&xl,  g_xl);
    cudaGetSymbolAddress((void**)&mh,  g_mh);  cudaGetSymbolAddress((void**)&ml,  g_ml);
    cudaGetSymbolAddress((void**)&wqh, g_wqh); cudaGetSymbolAddress((void**)&wql, g_wql);
    cudaGetSymbolAddress((void**)&wkh, g_wkh); cudaGetSymbolAddress((void**)&wkl, g_wkl);

    cudaFuncSetAttribute(tgemm_bf16_3t,
                         cudaFuncAttributeMaxDynamicSharedMemorySize, BSMEM);
    cudaFuncSetAttribute(tgemm_tf32<false>,
                         cudaFuncAttributeMaxDynamicSharedMemorySize, GSMEM_BYTES);
    cudaFuncSetAttribute(tgemm_tf32<true>,
                         cudaFuncAttributeMaxDynamicSharedMemorySize, GSMEM_BYTES);

    sp_kernel<<<1, CC>>>(scale);

    const int NW4 = CC * CC / 4;
    split_kernel<<<(RQ * CC / 4 + 255) / 256, 256>>>(x,   xh, xl, RQ * CC / 4);
    split_kernel<<<(RM * CC / 4 + 255) / 256, 256>>>(mem, mh, ml, RM * CC / 4);
    split_kernel<<<(NW4 + 255) / 256, 256>>>(w_q, wqh, wql, NW4);
    split_kernel<<<(NW4 + 255) / 256, 256>>>(w_k, wkh, wkl, NW4);
    round_tf32_kernel<<<(RM * CC / 4 + 255) / 256, 256>>>(mem, pmr, RM * CC / 4);
    round_tf32_kernel<<<(NW4 + 255) / 256, 256>>>(w_v, pwvr, NW4);
    round_tf32_kernel<<<(NW4 + 255) / 256, 256>>>(w_p, pwpr, NW4);

    // q,k: bf16 3-term split, 64x64 warp tiles
    tgemm_bf16_3t<<<dim3(RQ / 128, CC / 128), 128, BSMEM>>>(xh, xl, wqh, wql, pq);
    tgemm_bf16_3t<<<dim3(RM / 128, CC / 128), 128, BSMEM>>>(mh, ml, wkh, wkl, pk);
    // v: tf32 on pre-rounded operands, 64x64 warp tiles
    tgemm_tf32<false><<<dim3(RM / 128, CC / 128), 128, GSMEM_BYTES>>>(pmr, pwvr, nullptr, pv, RM);

    process_kernel<<<RQ, 256>>>(pq);
    process_kernel<<<RM, 256>>>(pk);

    kmean_part_kernel<<<dim3(64, BB), CC>>>();
    kmean_reduce_kernel<<<BB, CC>>>();

    kv_part_kernel<<<dim3(BB * HH, 16), 256>>>();
    kv_reduce_kernel<<<BB * HH, 256>>>();

    transpose_to_planes_kernel<<<dim3(NM / 32, CC / 32, BB), dim3(32, 8)>>>();
    dwconv_kernel<<<dim3(CC, BB), 256>>>(dwc_w, dwc_b);
    transpose_from_planes_kernel<<<dim3(NM / 32, CC / 32, BB), dim3(32, 8)>>>();

    attn_epilogue_kernel<<<dim3(NX / 64, HH, BB), 256>>>(pop);

    // proj: tf32 on pre-rounded operands
    tgemm_tf32<true><<<dim3(RQ / 128, CC / 128), 128, GSMEM_BYTES>>>(pop, pwpr, b_p, out, RQ);
}